// round 5
// baseline (speedup 1.0000x reference)
#include <cuda_runtime.h>
#include <cuda_bf16.h>
#include <cstdint>

// ============================================================================
// TNLayer, round 5: A fragments loaded DIRECTLY from global memory (no A smem,
// no cp.async, no per-tile barriers). Warps are fully independent.
//
//  h0[n,b]   = sum_i x0[n,i] t0[i,b]              (GEMM1: N=16, K=32)
//  h1[n,b,o] = sum_j x1[n,j] t1[j,b,o]            (GEMM2: N=104, K=32)
//  c[n,o]    = sum_b h0 * h1 + bias[o]; sigmoid
//
// B (smem, built once): same N-permuted layout as round 4:
//   B0 rows 0..15  : t0^T (rows 10..15 zero)
//   B1 even blocks : col 8b+o (b=0..9, o=0..7) -> thread-local epilogue
//   B1 o89 blocks  : col 80+8q+c (b=4q+c/2, o=8+c%2) -> quad bfly reduce
// ============================================================================

#define NTHREADS 128
#define NTILES   16384            // 1048576 / 64
#define GRID_X   592              // 148 SMs * 4 persistent CTAs
#define B_STRIDE 80               // bytes per B row (40 bf16)
#define OFF_B1   (16 * B_STRIDE)  // B0: 16 rows, then B1: 104 rows

static __device__ __forceinline__ void mma_bf16(float& c0, float& c1, float& c2, float& c3,
                                                uint32_t a0, uint32_t a1, uint32_t a2, uint32_t a3,
                                                uint32_t b0, uint32_t b1) {
    asm volatile(
        "mma.sync.aligned.m16n8k16.row.col.f32.bf16.bf16.f32 "
        "{%0,%1,%2,%3}, {%4,%5,%6,%7}, {%8,%9}, {%0,%1,%2,%3};"
        : "+f"(c0), "+f"(c1), "+f"(c2), "+f"(c3)
        : "r"(a0), "r"(a1), "r"(a2), "r"(a3), "r"(b0), "r"(b1));
}
static __device__ __forceinline__ uint32_t packbf(float lo, float hi) {
    __nv_bfloat162 p = __floats2bfloat162_rn(lo, hi);
    return *reinterpret_cast<uint32_t*>(&p);
}
static __device__ __forceinline__ float sigmoidf_(float c) {
    return __fdividef(1.0f, 1.0f + __expf(-c));
}

__global__ void __launch_bounds__(NTHREADS, 4)
tn_kernel(const float* __restrict__ x,
          const float* __restrict__ t0,
          const float* __restrict__ t1,
          const float* __restrict__ bias,
          float* __restrict__ out)
{
    __shared__ __align__(16) uint8_t sB[(16 + 104) * B_STRIDE];

    const int tid  = threadIdx.x;
    const int lane = tid & 31;
    const int w    = tid >> 5;
    const int g    = lane >> 2;     // 0..7
    const int t    = lane & 3;      // 0..3
    const int r0   = w * 16;

    // ---------------- one-time B setup ----------------
    for (int i = tid; i < (int)sizeof(sB) / 4; i += NTHREADS)
        ((uint32_t*)sB)[i] = 0u;
    __syncthreads();
    // B0 rows 0..9: B0[b][k=i] = t0[i,b]
    for (int idx = tid; idx < 280; idx += NTHREADS) {
        int i = idx / 10, b = idx % 10;
        *(__nv_bfloat16*)(sB + b * B_STRIDE + i * 2) = __float2bfloat16(t0[idx]);
    }
    // B1 even blocks: row 8b+o, k=j  (o = 0..7)
    for (int idx = tid; idx < 2240; idx += NTHREADS) {
        int j = idx / 80, r = idx % 80, b = r >> 3, o = r & 7;
        *(__nv_bfloat16*)(sB + OFF_B1 + (b * 8 + o) * B_STRIDE + j * 2) =
            __float2bfloat16(t1[j * 100 + b * 10 + o]);
    }
    // B1 o89 blocks: row 80+8q+c, b=4q+(c>>1), o=8+(c&1)
    for (int idx = tid; idx < 672; idx += NTHREADS) {
        int j = idx / 24, r = idx % 24, q = r >> 3, c = r & 7;
        int b = 4 * q + (c >> 1);
        if (b < 10)
            *(__nv_bfloat16*)(sB + OFF_B1 + (80 + q * 8 + c) * B_STRIDE + j * 2) =
                __float2bfloat16(t1[j * 100 + b * 10 + 8 + (c & 1)]);
    }
    const float bs0 = __ldg(bias + 2 * t);
    const float bs1 = __ldg(bias + 2 * t + 1);
    const float bs8 = __ldg(bias + 8);
    const float bs9 = __ldg(bias + 9);
    __syncthreads();

    const bool tlo = (t < 2);
    const float2 z2 = make_float2(0.f, 0.f);

    // ---------------- fully warp-independent tile loop ----------------
    for (int tile = blockIdx.x; tile < NTILES; tile += GRID_X) {
        const float* rg = x + ((size_t)tile * 64 + r0 + g) * 56;
        const float* rh = rg + 8 * 56;
        const int c0i = 2 * t;

        // ---- direct fragment loads (front-batched, MLP ~14) ----
        // slots: cols c0i + {0, 8, 16, 24*, 28, 36, 44, 52*}   (* = pad for t>=2)
        float2 vg0 = *(const float2*)(rg + c0i);
        float2 vh0 = *(const float2*)(rh + c0i);
        float2 vg1 = *(const float2*)(rg + c0i + 8);
        float2 vh1 = *(const float2*)(rh + c0i + 8);
        float2 vg2 = *(const float2*)(rg + c0i + 16);
        float2 vh2 = *(const float2*)(rh + c0i + 16);
        float2 vg3 = tlo ? *(const float2*)(rg + c0i + 24) : z2;
        float2 vh3 = tlo ? *(const float2*)(rh + c0i + 24) : z2;
        float2 wg0 = *(const float2*)(rg + c0i + 28);
        float2 wh0 = *(const float2*)(rh + c0i + 28);
        float2 wg1 = *(const float2*)(rg + c0i + 36);
        float2 wh1 = *(const float2*)(rh + c0i + 36);
        float2 wg2 = *(const float2*)(rg + c0i + 44);
        float2 wh2 = *(const float2*)(rh + c0i + 44);
        float2 wg3 = tlo ? *(const float2*)(rg + c0i + 52) : z2;
        float2 wh3 = tlo ? *(const float2*)(rh + c0i + 52) : z2;

        // ---- pack to bf16 fragments ----
        uint32_t ha[2][4], xa[2][4];
        ha[0][0] = packbf(vg0.x, vg0.y);  ha[0][1] = packbf(vh0.x, vh0.y);
        ha[0][2] = packbf(vg1.x, vg1.y);  ha[0][3] = packbf(vh1.x, vh1.y);
        ha[1][0] = packbf(vg2.x, vg2.y);  ha[1][1] = packbf(vh2.x, vh2.y);
        ha[1][2] = packbf(vg3.x, vg3.y);  ha[1][3] = packbf(vh3.x, vh3.y);
        xa[0][0] = packbf(wg0.x, wg0.y);  xa[0][1] = packbf(wh0.x, wh0.y);
        xa[0][2] = packbf(wg1.x, wg1.y);  xa[0][3] = packbf(wh1.x, wh1.y);
        xa[1][0] = packbf(wg2.x, wg2.y);  xa[1][1] = packbf(wh2.x, wh2.y);
        xa[1][2] = packbf(wg3.x, wg3.y);  xa[1][3] = packbf(wh3.x, wh3.y);

        // ---- GEMM1: h0 (N=16, K=32) ----
        float e00 = 0, e01 = 0, e02 = 0, e03 = 0;   // cols 0..7  (b = 2t,2t+1)
        float f00 = 0, f01 = 0, f02 = 0, f03 = 0;   // cols 8..15 (b = 8+2t)
#pragma unroll
        for (int kb = 0; kb < 2; kb++) {
            const uint8_t* br = sB + g * B_STRIDE + t * 4 + kb * 32;
            mma_bf16(e00, e01, e02, e03,
                     ha[kb][0], ha[kb][1], ha[kb][2], ha[kb][3],
                     *(const uint32_t*)br, *(const uint32_t*)(br + 16));
            const uint8_t* br2 = br + 8 * B_STRIDE;
            mma_bf16(f00, f01, f02, f03,
                     ha[kb][0], ha[kb][1], ha[kb][2], ha[kb][3],
                     *(const uint32_t*)br2, *(const uint32_t*)(br2 + 16));
        }

        // ---- GEMM2 even blocks, h0 fetched via in-loop width-4 shuffles ----
        float pA0g = 0, pA1g = 0, pA0h = 0, pA1h = 0;   // o = 2t, 2t+1
#pragma unroll
        for (int e = 0; e < 10; e++) {
            float c0 = 0, c1 = 0, c2 = 0, c3 = 0;
#pragma unroll
            for (int kb = 0; kb < 2; kb++) {
                const uint8_t* br = sB + OFF_B1 + (e * 8 + g) * B_STRIDE
                                    + t * 4 + kb * 32;
                mma_bf16(c0, c1, c2, c3,
                         xa[kb][0], xa[kb][1], xa[kb][2], xa[kb][3],
                         *(const uint32_t*)br, *(const uint32_t*)(br + 16));
            }
            float h0g_e, h0h_e;
            if (e < 8) {
                h0g_e = __shfl_sync(0xffffffffu, (e & 1) ? e01 : e00, e >> 1, 4);
                h0h_e = __shfl_sync(0xffffffffu, (e & 1) ? e03 : e02, e >> 1, 4);
            } else {
                h0g_e = __shfl_sync(0xffffffffu, (e & 1) ? f01 : f00, 0, 4);
                h0h_e = __shfl_sync(0xffffffffu, (e & 1) ? f03 : f02, 0, 4);
            }
            pA0g = fmaf(h0g_e, c0, pA0g);
            pA1g = fmaf(h0g_e, c1, pA1g);
            pA0h = fmaf(h0h_e, c2, pA0h);
            pA1h = fmaf(h0h_e, c3, pA1h);
        }

        // ---- GEMM2 o89 blocks: b = 4q + t, quad bfly reduce ----
        float p8g = 0, p9g = 0, p8h = 0, p9h = 0;
#pragma unroll
        for (int q = 0; q < 3; q++) {
            float c0 = 0, c1 = 0, c2 = 0, c3 = 0;
#pragma unroll
            for (int kb = 0; kb < 2; kb++) {
                const uint8_t* br = sB + OFF_B1 + (80 + q * 8 + g) * B_STRIDE
                                    + t * 4 + kb * 32;
                mma_bf16(c0, c1, c2, c3,
                         xa[kb][0], xa[kb][1], xa[kb][2], xa[kb][3],
                         *(const uint32_t*)br, *(const uint32_t*)(br + 16));
            }
            // h0[4q+t]: owner lane 2q + (t>>1), component (t&1)
            int srcl = 2 * q + (t >> 1);
            float v0 = __shfl_sync(0xffffffffu, e00, srcl, 4);
            float v1 = __shfl_sync(0xffffffffu, e01, srcl, 4);
            float v2 = __shfl_sync(0xffffffffu, e02, srcl, 4);
            float v3 = __shfl_sync(0xffffffffu, e03, srcl, 4);
            float vg = (t & 1) ? v1 : v0;
            float vh = (t & 1) ? v3 : v2;
            p8g = fmaf(vg, c0, p8g);
            p9g = fmaf(vg, c1, p9g);
            p8h = fmaf(vh, c2, p8h);
            p9h = fmaf(vh, c3, p9h);
        }
        p8g += __shfl_xor_sync(0xffffffffu, p8g, 1);
        p8g += __shfl_xor_sync(0xffffffffu, p8g, 2);
        p9g += __shfl_xor_sync(0xffffffffu, p9g, 1);
        p9g += __shfl_xor_sync(0xffffffffu, p9g, 2);
        p8h += __shfl_xor_sync(0xffffffffu, p8h, 1);
        p8h += __shfl_xor_sync(0xffffffffu, p8h, 2);
        p9h += __shfl_xor_sync(0xffffffffu, p9h, 1);
        p9h += __shfl_xor_sync(0xffffffffu, p9h, 2);

        // ---- sigmoid + store ----
        float* og = out + ((size_t)tile * 64 + r0 + g) * 10;
        *(float2*)(og + 2 * t) =
            make_float2(sigmoidf_(pA0g + bs0), sigmoidf_(pA1g + bs1));
        *(float2*)(og + 80 + 2 * t) =
            make_float2(sigmoidf_(pA0h + bs0), sigmoidf_(pA1h + bs1));
        if (t == 0) {
            *(float2*)(og + 8)  =
                make_float2(sigmoidf_(p8g + bs8), sigmoidf_(p9g + bs9));
            *(float2*)(og + 88) =
                make_float2(sigmoidf_(p8h + bs8), sigmoidf_(p9h + bs9));
        }
    }
}

extern "C" void kernel_launch(void* const* d_in, const int* in_sizes, int n_in,
                              void* d_out, int out_size) {
    const float* x    = (const float*)d_in[0];
    const float* t0   = (const float*)d_in[1];
    const float* t1   = (const float*)d_in[2];
    const float* bias = (const float*)d_in[3];
    float* out = (float*)d_out;
    tn_kernel<<<GRID_X, NTHREADS>>>(x, t0, t1, bias, out);
}

// round 6
// speedup vs baseline: 1.1426x; 1.1426x over previous
#include <cuda_runtime.h>
#include <cuda_bf16.h>
#include <cstdint>

// ============================================================================
// TNLayer, round 6: per-warp double-buffered cp.async A staging (coalesced),
// NO CTA barriers in the tile loop — warps fully independent.
//
//  h0[n,b]   = sum_i x0[n,i] t0[i,b]              (GEMM1: N=16, K=32)
//  h1[n,b,o] = sum_j x1[n,j] t1[j,b,o]            (GEMM2: N=104, K=32)
//  c[n,o]    = sum_b h0 * h1 + bias[o]; sigmoid
//
// B (smem, built once), N-permuted h1 layout:
//   B0 rows 0..15  : t0^T (k=0..27; rest zero)
//   B1 even blocks : col 8b+o (b=0..9, o=0..7)  -> thread-local epilogue
//   B1 o89 blocks  : col 80+8q+c (b=4q+c/2, o=8+c%2) -> quad bfly reduce
// A stage per warp: 16 rows x 288 B (72 f32; cols 56..71 zero pad), x2 stages.
// ============================================================================

#define NTHREADS 128
#define NTILES   16384            // 1048576 / 64
#define GRID_X   592              // 148 SMs * 4 persistent CTAs
#define B_STRIDE 80               // bytes per B row (40 bf16)
#define OFF_B1   (16 * B_STRIDE)
#define A_STRIDE 288              // bytes per A row (72 f32)
#define A_BUF    (16 * A_STRIDE)  // 4608 B per stage

static __device__ __forceinline__ uint32_t smem_u32(const void* p) {
    uint32_t a;
    asm("{ .reg .u64 t; cvta.to.shared.u64 t, %1; cvt.u32.u64 %0, t; }"
        : "=r"(a) : "l"(p));
    return a;
}
static __device__ __forceinline__ void cp_async16(uint32_t dst, const void* src) {
    asm volatile("cp.async.cg.shared.global [%0], [%1], 16;" :: "r"(dst), "l"(src));
}
static __device__ __forceinline__ void cp_commit() {
    asm volatile("cp.async.commit_group;" ::: "memory");
}
template <int N> static __device__ __forceinline__ void cp_wait() {
    asm volatile("cp.async.wait_group %0;" :: "n"(N) : "memory");
}
static __device__ __forceinline__ void mma_bf16(float& c0, float& c1, float& c2, float& c3,
                                                uint32_t a0, uint32_t a1, uint32_t a2, uint32_t a3,
                                                uint32_t b0, uint32_t b1) {
    asm volatile(
        "mma.sync.aligned.m16n8k16.row.col.f32.bf16.bf16.f32 "
        "{%0,%1,%2,%3}, {%4,%5,%6,%7}, {%8,%9}, {%0,%1,%2,%3};"
        : "+f"(c0), "+f"(c1), "+f"(c2), "+f"(c3)
        : "r"(a0), "r"(a1), "r"(a2), "r"(a3), "r"(b0), "r"(b1));
}
static __device__ __forceinline__ uint32_t packbf(float lo, float hi) {
    __nv_bfloat162 p = __floats2bfloat162_rn(lo, hi);
    return *reinterpret_cast<uint32_t*>(&p);
}
static __device__ __forceinline__ float sigmoidf_(float c) {
    return __fdividef(1.0f, 1.0f + __expf(-c));
}

__global__ void __launch_bounds__(NTHREADS, 4)
tn_kernel(const float* __restrict__ x,
          const float* __restrict__ t0,
          const float* __restrict__ t1,
          const float* __restrict__ bias,
          float* __restrict__ out)
{
    __shared__ __align__(16) uint8_t sA[4][2][A_BUF];   // [warp][stage]
    __shared__ __align__(16) uint8_t sB[(16 + 104) * B_STRIDE];

    const int tid  = threadIdx.x;
    const int lane = tid & 31;
    const int w    = tid >> 5;
    const int g    = lane >> 2;     // 0..7
    const int t    = lane & 3;      // 0..3
    const int r0   = w * 16;

    // ---------------- one-time setup ----------------
    for (int i = tid; i < (int)sizeof(sB) / 4; i += NTHREADS)
        ((uint32_t*)sB)[i] = 0u;
    // zero A pad cols 56..71 in all 8 stages (cp.async never writes there)
    for (int i = tid; i < 8 * 16 * 16; i += NTHREADS) {
        int buf = i >> 8, row = (i >> 4) & 15, c = i & 15;
        *(float*)(&sA[0][0][0] + buf * A_BUF + row * A_STRIDE + (56 + c) * 4) = 0.f;
    }
    __syncthreads();
    // B0 rows 0..9: B0[b][k=i] = t0[i,b]
    for (int idx = tid; idx < 280; idx += NTHREADS) {
        int i = idx / 10, b = idx % 10;
        *(__nv_bfloat16*)(sB + b * B_STRIDE + i * 2) = __float2bfloat16(t0[idx]);
    }
    // B1 even blocks: row 8b+o, k=j
    for (int idx = tid; idx < 2240; idx += NTHREADS) {
        int j = idx / 80, r = idx % 80, b = r >> 3, o = r & 7;
        *(__nv_bfloat16*)(sB + OFF_B1 + (b * 8 + o) * B_STRIDE + j * 2) =
            __float2bfloat16(t1[j * 100 + b * 10 + o]);
    }
    // B1 o89 blocks: row 80+8q+c, b=4q+(c>>1), o=8+(c&1)
    for (int idx = tid; idx < 672; idx += NTHREADS) {
        int j = idx / 24, r = idx % 24, q = r >> 3, c = r & 7;
        int b = 4 * q + (c >> 1);
        if (b < 10)
            *(__nv_bfloat16*)(sB + OFF_B1 + (80 + q * 8 + c) * B_STRIDE + j * 2) =
                __float2bfloat16(t1[j * 100 + b * 10 + 8 + (c & 1)]);
    }
    const float bs0 = __ldg(bias + 2 * t);
    const float bs1 = __ldg(bias + 2 * t + 1);
    const float bs8 = __ldg(bias + 8);
    const float bs9 = __ldg(bias + 9);
    __syncthreads();

    const uint32_t a0u = smem_u32(&sA[w][0][0]);
    const uint32_t a1u = smem_u32(&sA[w][1][0]);

    // per-warp coalesced prefetch: 224 float4 over 32 lanes (7 each)
    auto prefetch = [&](int tl, uint32_t dstu) {
        const float4* src = (const float4*)x + (size_t)tl * 896 + r0 * 14;
#pragma unroll
        for (int i = 0; i < 7; i++) {
            int idx = lane + i * 32;          // 0..223
            int row = idx / 14, c4 = idx % 14;
            cp_async16(dstu + row * A_STRIDE + c4 * 16, src + idx);
        }
        cp_commit();
    };

    int tile = blockIdx.x;
    prefetch(tile, a0u);
    int buf = 0;

    // ---------------- warp-independent tile loop ----------------
    for (; tile < NTILES; tile += GRID_X) {
        int nt = tile + GRID_X;
        if (nt < NTILES) { prefetch(nt, buf ? a0u : a1u); cp_wait<1>(); }
        else             { cp_wait<0>(); }
        __syncwarp();

        const float* Ag = (const float*)(&sA[w][buf][0] + g * A_STRIDE);
        const float* Ah = (const float*)((const uint8_t*)Ag + 8 * A_STRIDE);
        const int c0i = 2 * t;

        // ---- fragment loads + pack ----
        uint32_t ha[2][4], xa[2][4];
#pragma unroll
        for (int kb = 0; kb < 2; kb++) {
            const int k0 = c0i + 16 * kb;
            float2 vg0 = *(const float2*)(Ag + k0);
            float2 vh0 = *(const float2*)(Ah + k0);
            float2 vg1 = *(const float2*)(Ag + k0 + 8);
            float2 vh1 = *(const float2*)(Ah + k0 + 8);
            ha[kb][0] = packbf(vg0.x, vg0.y);
            ha[kb][1] = packbf(vh0.x, vh0.y);
            ha[kb][2] = packbf(vg1.x, vg1.y);
            ha[kb][3] = packbf(vh1.x, vh1.y);
            const int k1 = k0 + 28;
            float2 wg0 = *(const float2*)(Ag + k1);
            float2 wh0 = *(const float2*)(Ah + k1);
            float2 wg1 = *(const float2*)(Ag + k1 + 8);
            float2 wh1 = *(const float2*)(Ah + k1 + 8);
            xa[kb][0] = packbf(wg0.x, wg0.y);
            xa[kb][1] = packbf(wh0.x, wh0.y);
            xa[kb][2] = packbf(wg1.x, wg1.y);
            xa[kb][3] = packbf(wh1.x, wh1.y);
        }

        // ---- GEMM1: h0 (N=16, K=32) ----
        float e00 = 0, e01 = 0, e02 = 0, e03 = 0;   // cols 0..7  (b = 2t,2t+1)
        float f00 = 0, f01 = 0, f02 = 0, f03 = 0;   // cols 8..15 (b = 8+2t)
#pragma unroll
        for (int kb = 0; kb < 2; kb++) {
            const uint8_t* br = sB + g * B_STRIDE + t * 4 + kb * 32;
            mma_bf16(e00, e01, e02, e03,
                     ha[kb][0], ha[kb][1], ha[kb][2], ha[kb][3],
                     *(const uint32_t*)br, *(const uint32_t*)(br + 16));
            const uint8_t* br2 = br + 8 * B_STRIDE;
            mma_bf16(f00, f01, f02, f03,
                     ha[kb][0], ha[kb][1], ha[kb][2], ha[kb][3],
                     *(const uint32_t*)br2, *(const uint32_t*)(br2 + 16));
        }

        // ---- GEMM2 even blocks, thread-local contraction ----
        float pA0g = 0, pA1g = 0, pA0h = 0, pA1h = 0;   // o = 2t, 2t+1
#pragma unroll
        for (int e = 0; e < 10; e++) {
            float c0 = 0, c1 = 0, c2 = 0, c3 = 0;
#pragma unroll
            for (int kb = 0; kb < 2; kb++) {
                const uint8_t* br = sB + OFF_B1 + (e * 8 + g) * B_STRIDE
                                    + t * 4 + kb * 32;
                mma_bf16(c0, c1, c2, c3,
                         xa[kb][0], xa[kb][1], xa[kb][2], xa[kb][3],
                         *(const uint32_t*)br, *(const uint32_t*)(br + 16));
            }
            float h0g_e, h0h_e;
            if (e < 8) {
                h0g_e = __shfl_sync(0xffffffffu, (e & 1) ? e01 : e00, e >> 1, 4);
                h0h_e = __shfl_sync(0xffffffffu, (e & 1) ? e03 : e02, e >> 1, 4);
            } else {
                h0g_e = __shfl_sync(0xffffffffu, (e & 1) ? f01 : f00, 0, 4);
                h0h_e = __shfl_sync(0xffffffffu, (e & 1) ? f03 : f02, 0, 4);
            }
            pA0g = fmaf(h0g_e, c0, pA0g);
            pA1g = fmaf(h0g_e, c1, pA1g);
            pA0h = fmaf(h0h_e, c2, pA0h);
            pA1h = fmaf(h0h_e, c3, pA1h);
        }

        // ---- GEMM2 o89 blocks: b = 4q + t, quad bfly reduce ----
        float p8g = 0, p9g = 0, p8h = 0, p9h = 0;
#pragma unroll
        for (int q = 0; q < 3; q++) {
            float c0 = 0, c1 = 0, c2 = 0, c3 = 0;
#pragma unroll
            for (int kb = 0; kb < 2; kb++) {
                const uint8_t* br = sB + OFF_B1 + (80 + q * 8 + g) * B_STRIDE
                                    + t * 4 + kb * 32;
                mma_bf16(c0, c1, c2, c3,
                         xa[kb][0], xa[kb][1], xa[kb][2], xa[kb][3],
                         *(const uint32_t*)br, *(const uint32_t*)(br + 16));
            }
            int srcl = 2 * q + (t >> 1);
            float v0 = __shfl_sync(0xffffffffu, e00, srcl, 4);
            float v1 = __shfl_sync(0xffffffffu, e01, srcl, 4);
            float v2 = __shfl_sync(0xffffffffu, e02, srcl, 4);
            float v3 = __shfl_sync(0xffffffffu, e03, srcl, 4);
            float vg = (t & 1) ? v1 : v0;
            float vh = (t & 1) ? v3 : v2;
            p8g = fmaf(vg, c0, p8g);
            p9g = fmaf(vg, c1, p9g);
            p8h = fmaf(vh, c2, p8h);
            p9h = fmaf(vh, c3, p9h);
        }
        p8g += __shfl_xor_sync(0xffffffffu, p8g, 1);
        p8g += __shfl_xor_sync(0xffffffffu, p8g, 2);
        p9g += __shfl_xor_sync(0xffffffffu, p9g, 1);
        p9g += __shfl_xor_sync(0xffffffffu, p9g, 2);
        p8h += __shfl_xor_sync(0xffffffffu, p8h, 1);
        p8h += __shfl_xor_sync(0xffffffffu, p8h, 2);
        p9h += __shfl_xor_sync(0xffffffffu, p9h, 1);
        p9h += __shfl_xor_sync(0xffffffffu, p9h, 2);

        // ---- sigmoid + store ----
        float* og = out + ((size_t)tile * 64 + r0 + g) * 10;
        *(float2*)(og + 2 * t) =
            make_float2(sigmoidf_(pA0g + bs0), sigmoidf_(pA1g + bs1));
        *(float2*)(og + 80 + 2 * t) =
            make_float2(sigmoidf_(pA0h + bs0), sigmoidf_(pA1h + bs1));
        if (t == 0) {
            *(float2*)(og + 8)  =
                make_float2(sigmoidf_(p8g + bs8), sigmoidf_(p9g + bs9));
            *(float2*)(og + 88) =
                make_float2(sigmoidf_(p8h + bs8), sigmoidf_(p9h + bs9));
        }

        __syncwarp();     // lanes done with buf before next iter's prefetch reuses it
        buf ^= 1;
    }
}

extern "C" void kernel_launch(void* const* d_in, const int* in_sizes, int n_in,
                              void* d_out, int out_size) {
    const float* x    = (const float*)d_in[0];
    const float* t0   = (const float*)d_in[1];
    const float* t1   = (const float*)d_in[2];
    const float* bias = (const float*)d_in[3];
    float* out = (float*)d_out;
    tn_kernel<<<GRID_X, NTHREADS>>>(x, t0, t1, bias, out);
}

// round 7
// speedup vs baseline: 1.1831x; 1.0354x over previous
#include <cuda_runtime.h>
#include <cuda_bf16.h>
#include <cstdint>

// ============================================================================
// TNLayer, round 7: M=32 per warp (two m-tiles sharing every B fragment load),
// dense 224B A staging (no pad, conflict-free by 28g+t bank bijection),
// per-warp double-buffered cp.async, no CTA barriers in the loop.
//
//  h0[n,b]   = sum_i x0[n,i] t0[i,b]              (GEMM1: N=16, K=32)
//  h1[n,b,o] = sum_j x1[n,j] t1[j,b,o]            (GEMM2: N=104, K=32)
//  c[n,o]    = sum_b h0 * h1 + bias[o]; sigmoid
//
// B (smem, built once), N-permuted h1 layout (as rounds 4-6):
//   B0 rows 0..15  : t0^T (k=0..27; rest zero)
//   B1 even blocks : col 8b+o (b=0..9, o=0..7)  -> thread-local epilogue
//   B1 o89 blocks  : col 80+8q+c (b=4q+c/2, o=8+c%2) -> quad bfly reduce
// ============================================================================

#define NTHREADS 128
#define NTILES   8192             // 1048576 / 128
#define GRID_X   444              // 148 SMs * 3 persistent CTAs
#define B_STRIDE 80               // bytes per B row (40 bf16)
#define OFF_B1v  (16 * B_STRIDE)
#define A_STRIDE 224              // bytes per A row = 56 f32, DENSE
#define A_BUF    (32 * A_STRIDE)  // 7168 B per stage (32 rows)

#define OFF_A    0
#define OFF_B    (4 * 2 * A_BUF + 16)           // 57360 (16B guard after sA)
#define SMEM_BYTES (OFF_B + (16 + 104) * B_STRIDE)  // 66960

static __device__ __forceinline__ uint32_t smem_u32(const void* p) {
    uint32_t a;
    asm("{ .reg .u64 t; cvta.to.shared.u64 t, %1; cvt.u32.u64 %0, t; }"
        : "=r"(a) : "l"(p));
    return a;
}
static __device__ __forceinline__ void cp_async16(uint32_t dst, const void* src) {
    asm volatile("cp.async.cg.shared.global [%0], [%1], 16;" :: "r"(dst), "l"(src));
}
static __device__ __forceinline__ void cp_commit() {
    asm volatile("cp.async.commit_group;" ::: "memory");
}
template <int N> static __device__ __forceinline__ void cp_wait() {
    asm volatile("cp.async.wait_group %0;" :: "n"(N) : "memory");
}
static __device__ __forceinline__ void mma_bf16(float& c0, float& c1, float& c2, float& c3,
                                                uint32_t a0, uint32_t a1, uint32_t a2, uint32_t a3,
                                                uint32_t b0, uint32_t b1) {
    asm volatile(
        "mma.sync.aligned.m16n8k16.row.col.f32.bf16.bf16.f32 "
        "{%0,%1,%2,%3}, {%4,%5,%6,%7}, {%8,%9}, {%0,%1,%2,%3};"
        : "+f"(c0), "+f"(c1), "+f"(c2), "+f"(c3)
        : "r"(a0), "r"(a1), "r"(a2), "r"(a3), "r"(b0), "r"(b1));
}
static __device__ __forceinline__ uint32_t packbf(float lo, float hi) {
    __nv_bfloat162 p = __floats2bfloat162_rn(lo, hi);
    return *reinterpret_cast<uint32_t*>(&p);
}
static __device__ __forceinline__ float sigmoidf_(float c) {
    return __fdividef(1.0f, 1.0f + __expf(-c));
}

__global__ void __launch_bounds__(NTHREADS, 3)
tn_kernel(const float* __restrict__ x,
          const float* __restrict__ t0,
          const float* __restrict__ t1,
          const float* __restrict__ bias,
          float* __restrict__ out)
{
    extern __shared__ __align__(16) uint8_t smem[];
    uint8_t* sB = smem + OFF_B;

    const int tid  = threadIdx.x;
    const int lane = tid & 31;
    const int w    = tid >> 5;
    const int g    = lane >> 2;     // 0..7
    const int t    = lane & 3;      // 0..3
    const int r0   = w * 32;        // this warp's 32-sample base row

    // ---------------- one-time setup ----------------
    // zero entire A region + guard (makes any racy/tail read finite)
    for (int i = tid; i < OFF_B / 4; i += NTHREADS)
        ((uint32_t*)smem)[i] = 0u;
    for (int i = tid; i < (16 + 104) * B_STRIDE / 4; i += NTHREADS)
        ((uint32_t*)sB)[i] = 0u;
    __syncthreads();
    // B0 rows 0..9: B0[b][k=i] = t0[i,b]
    for (int idx = tid; idx < 280; idx += NTHREADS) {
        int i = idx / 10, b = idx % 10;
        *(__nv_bfloat16*)(sB + b * B_STRIDE + i * 2) = __float2bfloat16(t0[idx]);
    }
    // B1 even blocks: row 8b+o, k=j
    for (int idx = tid; idx < 2240; idx += NTHREADS) {
        int j = idx / 80, r = idx % 80, b = r >> 3, o = r & 7;
        *(__nv_bfloat16*)(sB + OFF_B1v + (b * 8 + o) * B_STRIDE + j * 2) =
            __float2bfloat16(t1[j * 100 + b * 10 + o]);
    }
    // B1 o89 blocks: row 80+8q+c, b=4q+(c>>1), o=8+(c&1)
    for (int idx = tid; idx < 672; idx += NTHREADS) {
        int j = idx / 24, r = idx % 24, q = r >> 3, c = r & 7;
        int b = 4 * q + (c >> 1);
        if (b < 10)
            *(__nv_bfloat16*)(sB + OFF_B1v + (80 + q * 8 + c) * B_STRIDE + j * 2) =
                __float2bfloat16(t1[j * 100 + b * 10 + 8 + (c & 1)]);
    }
    const float bs0 = __ldg(bias + 2 * t);
    const float bs1 = __ldg(bias + 2 * t + 1);
    const float bs8 = __ldg(bias + 8);
    const float bs9 = __ldg(bias + 9);
    __syncthreads();

    uint8_t* aW = smem + w * (2 * A_BUF);
    const uint32_t a0u = smem_u32(aW);
    const uint32_t a1u = a0u + A_BUF;

    // per-warp coalesced prefetch: 32 rows * 56 f32 = 448 float4 (linear!)
    auto prefetch = [&](int tl, uint32_t dstu) {
        const float4* src = (const float4*)x + (size_t)tl * 1792 + r0 * 14;
#pragma unroll
        for (int i = 0; i < 14; i++) {
            int idx = lane + i * 32;
            cp_async16(dstu + idx * 16, src + idx);
        }
        cp_commit();
    };

    int tile = blockIdx.x;
    prefetch(tile, a0u);
    int buf = 0;

    // ---------------- warp-independent tile loop ----------------
    for (; tile < NTILES; tile += GRID_X) {
        int nt = tile + GRID_X;
        if (nt < NTILES) { prefetch(nt, buf ? a0u : a1u); cp_wait<1>(); }
        else             { cp_wait<0>(); }
        __syncwarp();

        const uint8_t* ab = aW + buf * A_BUF;
        const int c0i = 2 * t;

        // ---- fragment loads + pack, both subtiles ----
        uint32_t ha[2][2][4], xa[2][2][4];   // [sub][kb][slot]
#pragma unroll
        for (int s = 0; s < 2; s++) {
            const float* Ag = (const float*)(ab + (s * 16 + g) * A_STRIDE);
            const float* Ah = (const float*)(ab + (s * 16 + g + 8) * A_STRIDE);
#pragma unroll
            for (int kb = 0; kb < 2; kb++) {
                const int k0 = c0i + 16 * kb;
                float2 v0 = *(const float2*)(Ag + k0);
                float2 v1 = *(const float2*)(Ah + k0);
                float2 v2 = *(const float2*)(Ag + k0 + 8);
                float2 v3 = *(const float2*)(Ah + k0 + 8);
                ha[s][kb][0] = packbf(v0.x, v0.y);
                ha[s][kb][1] = packbf(v1.x, v1.y);
                ha[s][kb][2] = packbf(v2.x, v2.y);
                ha[s][kb][3] = packbf(v3.x, v3.y);
                const int k1 = k0 + 28;
                float2 w0 = *(const float2*)(Ag + k1);
                float2 w1 = *(const float2*)(Ah + k1);
                float2 w2 = *(const float2*)(Ag + k1 + 8);
                float2 w3 = *(const float2*)(Ah + k1 + 8);
                xa[s][kb][0] = packbf(w0.x, w0.y);
                xa[s][kb][1] = packbf(w1.x, w1.y);
                xa[s][kb][2] = packbf(w2.x, w2.y);
                xa[s][kb][3] = packbf(w3.x, w3.y);
            }
        }

        // ---- GEMM1: h0 (N=16, K=32), B loads shared across subtiles ----
        float eA[2][4] = {{0,0,0,0},{0,0,0,0}};   // cols 0..7  (b = 2t,2t+1)
        float fA[2][4] = {{0,0,0,0},{0,0,0,0}};   // cols 8..15 (b = 8+2t)
#pragma unroll
        for (int kb = 0; kb < 2; kb++) {
            const uint8_t* br = sB + g * B_STRIDE + t * 4 + kb * 32;
            uint32_t b0 = *(const uint32_t*)br;
            uint32_t b1 = *(const uint32_t*)(br + 16);
            uint32_t d0 = *(const uint32_t*)(br + 8 * B_STRIDE);
            uint32_t d1 = *(const uint32_t*)(br + 8 * B_STRIDE + 16);
#pragma unroll
            for (int s = 0; s < 2; s++) {
                mma_bf16(eA[s][0], eA[s][1], eA[s][2], eA[s][3],
                         ha[s][kb][0], ha[s][kb][1], ha[s][kb][2], ha[s][kb][3],
                         b0, b1);
                mma_bf16(fA[s][0], fA[s][1], fA[s][2], fA[s][3],
                         ha[s][kb][0], ha[s][kb][1], ha[s][kb][2], ha[s][kb][3],
                         d0, d1);
            }
        }

        // ---- GEMM2 even blocks, thread-local contraction ----
        float pA[2][4] = {{0,0,0,0},{0,0,0,0}};   // [sub][{o=2t g, o=2t+1 g, o=2t h, o=2t+1 h}]
#pragma unroll
        for (int e = 0; e < 10; e++) {
            const uint8_t* br = sB + OFF_B1v + (e * 8 + g) * B_STRIDE + t * 4;
            uint32_t b00 = *(const uint32_t*)br;
            uint32_t b01 = *(const uint32_t*)(br + 16);
            uint32_t b10 = *(const uint32_t*)(br + 32);
            uint32_t b11 = *(const uint32_t*)(br + 48);
#pragma unroll
            for (int s = 0; s < 2; s++) {
                float c0 = 0, c1 = 0, c2 = 0, c3 = 0;
                mma_bf16(c0, c1, c2, c3,
                         xa[s][0][0], xa[s][0][1], xa[s][0][2], xa[s][0][3],
                         b00, b01);
                mma_bf16(c0, c1, c2, c3,
                         xa[s][1][0], xa[s][1][1], xa[s][1][2], xa[s][1][3],
                         b10, b11);
                float h0g_e, h0h_e;
                if (e < 8) {
                    h0g_e = __shfl_sync(0xffffffffu, (e & 1) ? eA[s][1] : eA[s][0], e >> 1, 4);
                    h0h_e = __shfl_sync(0xffffffffu, (e & 1) ? eA[s][3] : eA[s][2], e >> 1, 4);
                } else {
                    h0g_e = __shfl_sync(0xffffffffu, (e & 1) ? fA[s][1] : fA[s][0], 0, 4);
                    h0h_e = __shfl_sync(0xffffffffu, (e & 1) ? fA[s][3] : fA[s][2], 0, 4);
                }
                pA[s][0] = fmaf(h0g_e, c0, pA[s][0]);
                pA[s][1] = fmaf(h0g_e, c1, pA[s][1]);
                pA[s][2] = fmaf(h0h_e, c2, pA[s][2]);
                pA[s][3] = fmaf(h0h_e, c3, pA[s][3]);
            }
        }

        // ---- GEMM2 o89 blocks: b = 4q + t, quad bfly reduce ----
        float p89[2][4] = {{0,0,0,0},{0,0,0,0}};  // [sub][{p8g,p9g,p8h,p9h}]
#pragma unroll
        for (int q = 0; q < 3; q++) {
            const uint8_t* br = sB + OFF_B1v + (80 + q * 8 + g) * B_STRIDE + t * 4;
            uint32_t b00 = *(const uint32_t*)br;
            uint32_t b01 = *(const uint32_t*)(br + 16);
            uint32_t b10 = *(const uint32_t*)(br + 32);
            uint32_t b11 = *(const uint32_t*)(br + 48);
            const int srcl = 2 * q + (t >> 1);
#pragma unroll
            for (int s = 0; s < 2; s++) {
                float c0 = 0, c1 = 0, c2 = 0, c3 = 0;
                mma_bf16(c0, c1, c2, c3,
                         xa[s][0][0], xa[s][0][1], xa[s][0][2], xa[s][0][3],
                         b00, b01);
                mma_bf16(c0, c1, c2, c3,
                         xa[s][1][0], xa[s][1][1], xa[s][1][2], xa[s][1][3],
                         b10, b11);
                float v0 = __shfl_sync(0xffffffffu, eA[s][0], srcl, 4);
                float v1 = __shfl_sync(0xffffffffu, eA[s][1], srcl, 4);
                float v2 = __shfl_sync(0xffffffffu, eA[s][2], srcl, 4);
                float v3 = __shfl_sync(0xffffffffu, eA[s][3], srcl, 4);
                float vg = (t & 1) ? v1 : v0;
                float vh = (t & 1) ? v3 : v2;
                p89[s][0] = fmaf(vg, c0, p89[s][0]);
                p89[s][1] = fmaf(vg, c1, p89[s][1]);
                p89[s][2] = fmaf(vh, c2, p89[s][2]);
                p89[s][3] = fmaf(vh, c3, p89[s][3]);
            }
        }
#pragma unroll
        for (int s = 0; s < 2; s++)
#pragma unroll
            for (int u = 0; u < 4; u++) {
                p89[s][u] += __shfl_xor_sync(0xffffffffu, p89[s][u], 1);
                p89[s][u] += __shfl_xor_sync(0xffffffffu, p89[s][u], 2);
            }

        // ---- sigmoid + store ----
#pragma unroll
        for (int s = 0; s < 2; s++) {
            float* og = out + ((size_t)tile * 128 + r0 + s * 16 + g) * 10;
            *(float2*)(og + 2 * t) =
                make_float2(sigmoidf_(pA[s][0] + bs0), sigmoidf_(pA[s][1] + bs1));
            *(float2*)(og + 80 + 2 * t) =
                make_float2(sigmoidf_(pA[s][2] + bs0), sigmoidf_(pA[s][3] + bs1));
            if (t == 0) {
                *(float2*)(og + 8)  =
                    make_float2(sigmoidf_(p89[s][0] + bs8), sigmoidf_(p89[s][1] + bs9));
                *(float2*)(og + 88) =
                    make_float2(sigmoidf_(p89[s][2] + bs8), sigmoidf_(p89[s][3] + bs9));
            }
        }

        __syncwarp();
        buf ^= 1;
    }
}

extern "C" void kernel_launch(void* const* d_in, const int* in_sizes, int n_in,
                              void* d_out, int out_size) {
    const float* x    = (const float*)d_in[0];
    const float* t0   = (const float*)d_in[1];
    const float* t1   = (const float*)d_in[2];
    const float* bias = (const float*)d_in[3];
    float* out = (float*)d_out;

    cudaFuncSetAttribute(tn_kernel, cudaFuncAttributeMaxDynamicSharedMemorySize,
                         SMEM_BYTES);
    tn_kernel<<<GRID_X, NTHREADS, SMEM_BYTES>>>(x, t0, t1, bias, out);
}

// round 8
// speedup vs baseline: 1.2917x; 1.0918x over previous
#include <cuda_runtime.h>
#include <cuda_bf16.h>
#include <cstdint>

// ============================================================================
// TNLayer, round 8: single-buffered per-warp A stage (cp.async write lands at
// data-return, so refilling the same buffer after fragment-LDS is safe),
// B0 in registers, B1 fragment-major (LDS.128), 4 CTAs/SM.
//
//  h0[n,b]   = sum_i x0[n,i] t0[i,b]              (GEMM1: N=16, K=32)
//  h1[n,b,o] = sum_j x1[n,j] t1[j,b,o]            (GEMM2: N=104, K=32)
//  c[n,o]    = sum_b h0 * h1 + bias[o]; sigmoid
//
// B1 fragment-major blocks e = 0..12:
//   e = 0..9  : n = 8e+g -> b=e, o=g              (thread-local epilogue)
//   e = 10+q  : n = 80+8q+g -> b=4q+(g>>1), o=8+(g&1)  (quad bfly reduce)
// fragment word w of lane (g,t): j pair (2t+8w, 2t+8w+1), zero for j>=28.
// ============================================================================

#define NTHREADS 128
#define NTILES   8192             // 1048576 / 128
#define GRID_X   592              // 148 SMs * 4 persistent CTAs
#define A_STRIDE 224              // bytes per A row = 56 f32, dense
#define A_BUF    (32 * A_STRIDE)  // 7168 B single stage per warp
#define SBF_OFF  (4 * A_BUF + 16) // 16B zero guard after A region
#define SMEM_TOTAL (SBF_OFF + 13 * 512)   // 13 blocks * 32 lanes * 16B = 6656

static __device__ __forceinline__ uint32_t smem_u32(const void* p) {
    uint32_t a;
    asm("{ .reg .u64 t; cvta.to.shared.u64 t, %1; cvt.u32.u64 %0, t; }"
        : "=r"(a) : "l"(p));
    return a;
}
static __device__ __forceinline__ void cp_async16(uint32_t dst, const void* src) {
    asm volatile("cp.async.cg.shared.global [%0], [%1], 16;" :: "r"(dst), "l"(src));
}
static __device__ __forceinline__ void cp_commit() {
    asm volatile("cp.async.commit_group;" ::: "memory");
}
template <int N> static __device__ __forceinline__ void cp_wait() {
    asm volatile("cp.async.wait_group %0;" :: "n"(N) : "memory");
}
static __device__ __forceinline__ void mma_bf16(float& c0, float& c1, float& c2, float& c3,
                                                uint32_t a0, uint32_t a1, uint32_t a2, uint32_t a3,
                                                uint32_t b0, uint32_t b1) {
    asm volatile(
        "mma.sync.aligned.m16n8k16.row.col.f32.bf16.bf16.f32 "
        "{%0,%1,%2,%3}, {%4,%5,%6,%7}, {%8,%9}, {%0,%1,%2,%3};"
        : "+f"(c0), "+f"(c1), "+f"(c2), "+f"(c3)
        : "r"(a0), "r"(a1), "r"(a2), "r"(a3), "r"(b0), "r"(b1));
}
static __device__ __forceinline__ uint32_t packbf(float lo, float hi) {
    __nv_bfloat162 p = __floats2bfloat162_rn(lo, hi);
    return *reinterpret_cast<uint32_t*>(&p);
}
static __device__ __forceinline__ float sigmoidf_(float c) {
    return __fdividef(1.0f, 1.0f + __expf(-c));
}

__global__ void __launch_bounds__(NTHREADS, 4)
tn_kernel(const float* __restrict__ x,
          const float* __restrict__ t0,
          const float* __restrict__ t1,
          const float* __restrict__ bias,
          float* __restrict__ out)
{
    __shared__ __align__(16) uint8_t smem[SMEM_TOTAL];
    uint8_t* sBf = smem + SBF_OFF;

    const int tid  = threadIdx.x;
    const int lane = tid & 31;
    const int w    = tid >> 5;
    const int g    = lane >> 2;     // 0..7
    const int t    = lane & 3;      // 0..3
    const int r0   = w * 32;

    // ---------------- one-time setup ----------------
    // zero A region + guard (cp.async overwrites A fully each tile; guard stays 0)
    for (int i = tid; i < SBF_OFF / 4; i += NTHREADS)
        ((uint32_t*)smem)[i] = 0u;

    // B1 fragment-major fill: idx = e*128 + lane*4 + word
    for (int idx = tid; idx < 13 * 128; idx += NTHREADS) {
        int e = idx >> 7, ln = (idx >> 2) & 31, wd = idx & 3;
        int gg = ln >> 2, tt = ln & 3;
        int j0 = 2 * tt + 8 * wd;
        int b, o;
        if (e < 10) { b = e; o = gg; }
        else        { int q = e - 10; b = 4 * q + (gg >> 1); o = 8 + (gg & 1); }
        float f0 = 0.f, f1 = 0.f;
        if (b < 10) {
            if (j0 < 28)     f0 = t1[j0 * 100 + b * 10 + o];
            if (j0 + 1 < 28) f1 = t1[(j0 + 1) * 100 + b * 10 + o];
        }
        ((uint32_t*)sBf)[idx] = packbf(f0, f1);
    }

    // B0 (GEMM1) fragments into registers
    auto T0 = [&](int i, int b) -> float {
        return (i < 28 && b < 10) ? __ldg(t0 + i * 10 + b) : 0.f;
    };
    uint32_t gb[2][2], fb[2][2];
#pragma unroll
    for (int kb = 0; kb < 2; kb++) {
        int k = 2 * t + 16 * kb;
        gb[kb][0] = packbf(T0(k, g),     T0(k + 1, g));
        gb[kb][1] = packbf(T0(k + 8, g), T0(k + 9, g));
        fb[kb][0] = packbf(T0(k, 8 + g),     T0(k + 1, 8 + g));
        fb[kb][1] = packbf(T0(k + 8, 8 + g), T0(k + 9, 8 + g));
    }
    const float bs0 = __ldg(bias + 2 * t);
    const float bs1 = __ldg(bias + 2 * t + 1);
    const float bs8 = __ldg(bias + 8);
    const float bs9 = __ldg(bias + 9);
    __syncthreads();

    uint8_t* aW = smem + w * A_BUF;
    const uint32_t aWu = smem_u32(aW);

    // per-warp coalesced prefetch into the single stage (448 linear float4)
    auto prefetch = [&](int tl) {
        const float4* src = (const float4*)x + (size_t)tl * 1792 + r0 * 14;
#pragma unroll
        for (int i = 0; i < 14; i++) {
            int idx = lane + i * 32;
            cp_async16(aWu + idx * 16, src + idx);
        }
        cp_commit();
    };

    int tile = blockIdx.x;
    prefetch(tile);

    // ---------------- warp-independent tile loop ----------------
    for (; tile < NTILES; tile += GRID_X) {
        cp_wait<0>();
        __syncwarp();

        const int c0i = 2 * t;

        // ---- h0-part fragment loads + GEMM1 (B in registers) ----
        float eA[2][4] = {{0,0,0,0},{0,0,0,0}};   // cols 0..7  (b = 2t,2t+1)
        float fA[2][4] = {{0,0,0,0},{0,0,0,0}};   // cols 8..15 (b = 8+2t)
        uint32_t xa[2][2][4];                      // h1 A frags   [sub][kb][slot]
#pragma unroll
        for (int s = 0; s < 2; s++) {
            const float* Ag = (const float*)(aW + (s * 16 + g) * A_STRIDE);
            const float* Ah = (const float*)(aW + (s * 16 + g + 8) * A_STRIDE);
#pragma unroll
            for (int kb = 0; kb < 2; kb++) {
                const int k0 = c0i + 16 * kb;
                float2 v0 = *(const float2*)(Ag + k0);
                float2 v1 = *(const float2*)(Ah + k0);
                float2 v2 = *(const float2*)(Ag + k0 + 8);
                float2 v3 = *(const float2*)(Ah + k0 + 8);
                uint32_t a0 = packbf(v0.x, v0.y);
                uint32_t a1 = packbf(v1.x, v1.y);
                uint32_t a2 = packbf(v2.x, v2.y);
                uint32_t a3 = packbf(v3.x, v3.y);
                mma_bf16(eA[s][0], eA[s][1], eA[s][2], eA[s][3],
                         a0, a1, a2, a3, gb[kb][0], gb[kb][1]);
                mma_bf16(fA[s][0], fA[s][1], fA[s][2], fA[s][3],
                         a0, a1, a2, a3, fb[kb][0], fb[kb][1]);
                // h1 A frags (cols 28..; overflow cols hit zero-B lanes / guard)
                const int k1 = k0 + 28;
                float2 w0 = *(const float2*)(Ag + k1);
                float2 w1 = *(const float2*)(Ah + k1);
                float2 w2 = *(const float2*)(Ag + k1 + 8);
                float2 w3 = *(const float2*)(Ah + k1 + 8);
                xa[s][kb][0] = packbf(w0.x, w0.y);
                xa[s][kb][1] = packbf(w1.x, w1.y);
                xa[s][kb][2] = packbf(w2.x, w2.y);
                xa[s][kb][3] = packbf(w3.x, w3.y);
            }
        }

        // ---- all smem A reads done: refill the SAME buffer for next tile ----
        // (cp.async smem writes land at global-data return, far after these LDS)
        int nt = tile + GRID_X;
        if (nt < NTILES) prefetch(nt);

        // ---- GEMM2 even blocks (B1 via LDS.128), thread-local contraction ----
        float pA[2][4] = {{0,0,0,0},{0,0,0,0}};
#pragma unroll
        for (int e = 0; e < 10; e++) {
            uint4 bv = *(const uint4*)(sBf + e * 512 + lane * 16);
#pragma unroll
            for (int s = 0; s < 2; s++) {
                float c0 = 0, c1 = 0, c2 = 0, c3 = 0;
                mma_bf16(c0, c1, c2, c3,
                         xa[s][0][0], xa[s][0][1], xa[s][0][2], xa[s][0][3],
                         bv.x, bv.y);
                mma_bf16(c0, c1, c2, c3,
                         xa[s][1][0], xa[s][1][1], xa[s][1][2], xa[s][1][3],
                         bv.z, bv.w);
                float h0g_e, h0h_e;
                if (e < 8) {
                    h0g_e = __shfl_sync(0xffffffffu, (e & 1) ? eA[s][1] : eA[s][0], e >> 1, 4);
                    h0h_e = __shfl_sync(0xffffffffu, (e & 1) ? eA[s][3] : eA[s][2], e >> 1, 4);
                } else {
                    h0g_e = __shfl_sync(0xffffffffu, (e & 1) ? fA[s][1] : fA[s][0], 0, 4);
                    h0h_e = __shfl_sync(0xffffffffu, (e & 1) ? fA[s][3] : fA[s][2], 0, 4);
                }
                pA[s][0] = fmaf(h0g_e, c0, pA[s][0]);
                pA[s][1] = fmaf(h0g_e, c1, pA[s][1]);
                pA[s][2] = fmaf(h0h_e, c2, pA[s][2]);
                pA[s][3] = fmaf(h0h_e, c3, pA[s][3]);
            }
        }

        // ---- GEMM2 o89 blocks: b = 4q + t, quad bfly reduce ----
        float p89[2][4] = {{0,0,0,0},{0,0,0,0}};
#pragma unroll
        for (int q = 0; q < 3; q++) {
            uint4 bv = *(const uint4*)(sBf + (10 + q) * 512 + lane * 16);
            const int srcl = 2 * q + (t >> 1);
#pragma unroll
            for (int s = 0; s < 2; s++) {
                float c0 = 0, c1 = 0, c2 = 0, c3 = 0;
                mma_bf16(c0, c1, c2, c3,
                         xa[s][0][0], xa[s][0][1], xa[s][0][2], xa[s][0][3],
                         bv.x, bv.y);
                mma_bf16(c0, c1, c2, c3,
                         xa[s][1][0], xa[s][1][1], xa[s][1][2], xa[s][1][3],
                         bv.z, bv.w);
                float v0 = __shfl_sync(0xffffffffu, eA[s][0], srcl, 4);
                float v1 = __shfl_sync(0xffffffffu, eA[s][1], srcl, 4);
                float v2 = __shfl_sync(0xffffffffu, eA[s][2], srcl, 4);
                float v3 = __shfl_sync(0xffffffffu, eA[s][3], srcl, 4);
                float vg = (t & 1) ? v1 : v0;
                float vh = (t & 1) ? v3 : v2;
                p89[s][0] = fmaf(vg, c0, p89[s][0]);
                p89[s][1] = fmaf(vg, c1, p89[s][1]);
                p89[s][2] = fmaf(vh, c2, p89[s][2]);
                p89[s][3] = fmaf(vh, c3, p89[s][3]);
            }
        }
#pragma unroll
        for (int s = 0; s < 2; s++)
#pragma unroll
            for (int u = 0; u < 4; u++) {
                p89[s][u] += __shfl_xor_sync(0xffffffffu, p89[s][u], 1);
                p89[s][u] += __shfl_xor_sync(0xffffffffu, p89[s][u], 2);
            }

        // ---- sigmoid + store ----
#pragma unroll
        for (int s = 0; s < 2; s++) {
            float* og = out + ((size_t)tile * 128 + r0 + s * 16 + g) * 10;
            *(float2*)(og + 2 * t) =
                make_float2(sigmoidf_(pA[s][0] + bs0), sigmoidf_(pA[s][1] + bs1));
            *(float2*)(og + 80 + 2 * t) =
                make_float2(sigmoidf_(pA[s][2] + bs0), sigmoidf_(pA[s][3] + bs1));
            if (t == 0) {
                *(float2*)(og + 8)  =
                    make_float2(sigmoidf_(p89[s][0] + bs8), sigmoidf_(p89[s][1] + bs9));
                *(float2*)(og + 88) =
                    make_float2(sigmoidf_(p89[s][2] + bs8), sigmoidf_(p89[s][3] + bs9));
            }
        }
    }
}

extern "C" void kernel_launch(void* const* d_in, const int* in_sizes, int n_in,
                              void* d_out, int out_size) {
    const float* x    = (const float*)d_in[0];
    const float* t0   = (const float*)d_in[1];
    const float* t1   = (const float*)d_in[2];
    const float* bias = (const float*)d_in[3];
    float* out = (float*)d_out;
    tn_kernel<<<GRID_X, NTHREADS>>>(x, t0, t1, bias, out);
}